// round 2
// baseline (speedup 1.0000x reference)
#include <cuda_runtime.h>

// GIN model, algebraically restructured:
//   conv(x) = segment_sum(relu(x[src]@W1x + ea@W1e + b1), dst) @ W2 + (deg+1) * b2
// Per-node GEMMs + per-edge elementwise gather/scatter (L2-resident tables).
// NOTE: edge_index arrives as int32 (JAX canonicalizes int64 -> int32).

#define HD 128
#define MAX_N 100000
#define MAX_E 1600000

__device__ float g_P[(long long)MAX_N * HD];    // per-node pre-MLP table
__device__ float g_agg[(long long)MAX_N * HD];  // aggregation buffer
__device__ float g_h[(long long)MAX_N * HD];    // layer-1 output
__device__ float g_deg[MAX_N];                  // in-degree (float)

// ---------------------------------------------------------------------------
__global__ void zero_deg_kernel(float* __restrict__ deg, int N) {
    int i = blockIdx.x * blockDim.x + threadIdx.x;
    if (i < N) deg[i] = 0.0f;
}

__global__ void count_deg_kernel(const int* __restrict__ ei,
                                 float* __restrict__ deg, int E) {
    int e = blockIdx.x * blockDim.x + threadIdx.x;
    if (e < E) atomicAdd(&deg[ei[E + e]], 1.0f);  // dst row
}

// ---------------------------------------------------------------------------
// C[N,128] = A[N,K] @ W[K,128]   (K = 64 or 128, row-major W)
// optional: C += (deg[row]+1) * bias[col];  optional relu on C
// optional: aggOut[row,col] = relu(C_raw + sw0[col] + sw1[col] + sb[col])
//           (self-loop init of the aggregation buffer, ea = (1,1))
// block: 256 threads, tile 64 rows x 128 cols, each thread 4 rows x 8 cols.
__global__ __launch_bounds__(256)
void gemm_kernel(const float* __restrict__ A, const float* __restrict__ W,
                 float* __restrict__ C, int N, int K,
                 const float* __restrict__ bias, const float* __restrict__ deg,
                 int relu_flag,
                 float* __restrict__ aggOut,
                 const float* __restrict__ sw0, const float* __restrict__ sw1,
                 const float* __restrict__ sb)
{
    __shared__ float Ws[32][128];
    __shared__ float As[64][33];

    const int tid = threadIdx.x;
    const int tx = tid & 15;   // col group: cols [8*tx, 8*tx+8)
    const int ty = tid >> 4;   // row group: rows [4*ty, 4*ty+4)
    const int row0 = blockIdx.x * 64;

    float acc[4][8];
#pragma unroll
    for (int r = 0; r < 4; ++r)
#pragma unroll
        for (int j = 0; j < 8; ++j) acc[r][j] = 0.0f;

    for (int k0 = 0; k0 < K; k0 += 32) {
        // load W tile (32 x 128)
#pragma unroll
        for (int i = tid; i < 32 * 128; i += 256) {
            int kk = i >> 7, cc = i & 127;
            Ws[kk][cc] = W[(k0 + kk) * 128 + cc];
        }
        // load A tile (64 x 32)
#pragma unroll
        for (int i = tid; i < 64 * 32; i += 256) {
            int rr = i >> 5, kk = i & 31;
            int r = row0 + rr;
            As[rr][kk] = (r < N) ? A[(long long)r * K + k0 + kk] : 0.0f;
        }
        __syncthreads();
#pragma unroll
        for (int k = 0; k < 32; ++k) {
            float4 w0 = *(const float4*)&Ws[k][tx * 8];
            float4 w1 = *(const float4*)&Ws[k][tx * 8 + 4];
#pragma unroll
            for (int r = 0; r < 4; ++r) {
                float a = As[ty * 4 + r][k];
                acc[r][0] += a * w0.x; acc[r][1] += a * w0.y;
                acc[r][2] += a * w0.z; acc[r][3] += a * w0.w;
                acc[r][4] += a * w1.x; acc[r][5] += a * w1.y;
                acc[r][6] += a * w1.z; acc[r][7] += a * w1.w;
            }
        }
        __syncthreads();
    }

    const int c0 = tx * 8;
#pragma unroll
    for (int r = 0; r < 4; ++r) {
        int row = row0 + ty * 4 + r;
        if (row >= N) continue;
        float vout[8];
        float mult = 0.0f;
        if (bias) mult = deg ? (deg[row] + 1.0f) : 1.0f;
#pragma unroll
        for (int j = 0; j < 8; ++j) {
            float v = acc[r][j];
            if (bias) v += mult * bias[c0 + j];
            if (relu_flag) v = fmaxf(v, 0.0f);
            vout[j] = v;
        }
        float4* dst = (float4*)&C[(long long)row * 128 + c0];
        dst[0] = make_float4(vout[0], vout[1], vout[2], vout[3]);
        dst[1] = make_float4(vout[4], vout[5], vout[6], vout[7]);
        if (aggOut) {
            float aout[8];
#pragma unroll
            for (int j = 0; j < 8; ++j) {
                int c = c0 + j;
                aout[j] = fmaxf(acc[r][j] + sw0[c] + sw1[c] + sb[c], 0.0f);
            }
            float4* ad = (float4*)&aggOut[(long long)row * 128 + c0];
            ad[0] = make_float4(aout[0], aout[1], aout[2], aout[3]);
            ad[1] = make_float4(aout[4], aout[5], aout[6], aout[7]);
        }
    }
}

// ---------------------------------------------------------------------------
// Per-edge: agg[dst] += relu(P[src] + ea0*w0 + ea1*w1 + b)   (128 floats)
// One warp per edge, lane handles 4 consecutive floats, vector red.add.
__global__ __launch_bounds__(256)
void scatter_kernel(const int* __restrict__ ei,
                    const float* __restrict__ ea,
                    const float* __restrict__ P,
                    float* __restrict__ agg,
                    const float* __restrict__ w0,
                    const float* __restrict__ w1,
                    const float* __restrict__ b,
                    int E)
{
    const int lane = threadIdx.x & 31;
    const int c = lane * 4;
    const int warp = blockIdx.x * (blockDim.x >> 5) + (threadIdx.x >> 5);
    const int nwarps = gridDim.x * (blockDim.x >> 5);

    // per-lane constants (reused for every edge this warp processes)
    const float4 wa = *(const float4*)(w0 + c);
    const float4 wb = *(const float4*)(w1 + c);
    const float4 bb = *(const float4*)(b + c);

    for (int e = warp; e < E; e += nwarps) {
        int src = ei[e];
        int dst = ei[E + e];
        float ea0 = ea[2 * e];
        float ea1 = ea[2 * e + 1];
        float4 p = *(const float4*)(P + (long long)src * HD + c);
        float4 v;
        v.x = fmaxf(fmaf(ea0, wa.x, fmaf(ea1, wb.x, p.x + bb.x)), 0.0f);
        v.y = fmaxf(fmaf(ea0, wa.y, fmaf(ea1, wb.y, p.y + bb.y)), 0.0f);
        v.z = fmaxf(fmaf(ea0, wa.z, fmaf(ea1, wb.z, p.z + bb.z)), 0.0f);
        v.w = fmaxf(fmaf(ea0, wa.w, fmaf(ea1, wb.w, p.w + bb.w)), 0.0f);
        float* d = agg + (long long)dst * HD + c;
        asm volatile("red.global.add.v4.f32 [%0], {%1,%2,%3,%4};"
                     :: "l"(d), "f"(v.x), "f"(v.y), "f"(v.z), "f"(v.w)
                     : "memory");
    }
}

// ---------------------------------------------------------------------------
extern "C" void kernel_launch(void* const* d_in, const int* in_sizes, int n_in,
                              void* d_out, int out_size)
{
    const float* x   = (const float*)d_in[0];
    const int*   ei  = (const int*)d_in[1];     // int32 edge indices
    const float* ea  = (const float*)d_in[2];
    const float* W11 = (const float*)d_in[3];
    const float* b11 = (const float*)d_in[4];
    const float* W12 = (const float*)d_in[5];
    const float* b12 = (const float*)d_in[6];
    const float* W21 = (const float*)d_in[7];
    const float* b21 = (const float*)d_in[8];
    const float* W22 = (const float*)d_in[9];
    const float* b22 = (const float*)d_in[10];
    float* out = (float*)d_out;

    const int IN_DIM = 64;
    const int N = in_sizes[0] / IN_DIM;
    const int E = in_sizes[1] / 2;

    float* P   = nullptr;
    float* agg = nullptr;
    float* h   = nullptr;
    float* deg = nullptr;
    cudaGetSymbolAddress((void**)&P,   g_P);
    cudaGetSymbolAddress((void**)&agg, g_agg);
    cudaGetSymbolAddress((void**)&h,   g_h);
    cudaGetSymbolAddress((void**)&deg, g_deg);

    const int gemm_blocks = (N + 63) / 64;
    const int scat_blocks = 148 * 16;

    // degrees (same graph both layers)
    zero_deg_kernel<<<(N + 255) / 256, 256>>>(deg, N);
    count_deg_kernel<<<(E + 255) / 256, 256>>>(ei, deg, E);

    // ---- layer 1 ----
    // P = x @ W11[0:64];  agg = relu(P + W11[64] + W11[65] + b11) (self loop)
    gemm_kernel<<<gemm_blocks, 256>>>(x, W11, P, N, 64,
                                      nullptr, nullptr, 0,
                                      agg, W11 + 64 * 128, W11 + 65 * 128, b11);
    scatter_kernel<<<scat_blocks, 256>>>(ei, ea, P, agg,
                                         W11 + 64 * 128, W11 + 65 * 128, b11, E);
    // h = relu(agg @ W12 + (deg+1) * b12)
    gemm_kernel<<<gemm_blocks, 256>>>(agg, W12, h, N, 128,
                                      b12, deg, 1,
                                      nullptr, nullptr, nullptr, nullptr);

    // ---- layer 2 ----
    // P = h @ W21[0:128]; agg = relu(P + W21[128] + W21[129] + b21)
    gemm_kernel<<<gemm_blocks, 256>>>(h, W21, P, N, 128,
                                      nullptr, nullptr, 0,
                                      agg, W21 + 128 * 128, W21 + 129 * 128, b21);
    scatter_kernel<<<scat_blocks, 256>>>(ei, ea, P, agg,
                                         W21 + 128 * 128, W21 + 129 * 128, b21, E);
    // out = agg @ W22 + (deg+1) * b22
    gemm_kernel<<<gemm_blocks, 256>>>(agg, W22, out, N, 128,
                                      b22, deg, 0,
                                      nullptr, nullptr, nullptr, nullptr);
}

// round 3
// speedup vs baseline: 1.2074x; 1.2074x over previous
#include <cuda_runtime.h>

// GIN model, algebraically restructured:
//   conv(x) = segment_sum(relu(x[src]@W1x + ea@W1e + b1), dst) @ W2 + (deg+1) * b2
// Per-node GEMMs (fp32x2 packed FMA) + per-edge gather/scatter (L2-resident).

#define HD 128
#define MAX_N 100000
#define MAX_E 1600000

__device__ float g_P[(long long)MAX_N * HD];    // per-node pre-MLP table
__device__ float g_agg[(long long)MAX_N * HD];  // aggregation buffer
__device__ float g_h[(long long)MAX_N * HD];    // layer-1 output
__device__ float g_deg[MAX_N];                  // in-degree (float)

typedef unsigned long long ull;

__device__ __forceinline__ ull pk2(float x, float y) {
    ull r; asm("mov.b64 %0, {%1, %2};" : "=l"(r) : "f"(x), "f"(y)); return r;
}
__device__ __forceinline__ void upk2(ull v, float& x, float& y) {
    asm("mov.b64 {%0, %1}, %2;" : "=f"(x), "=f"(y) : "l"(v));
}
__device__ __forceinline__ ull fma2(ull a, ull b, ull c) {
    ull d; asm("fma.rn.f32x2 %0, %1, %2, %3;" : "=l"(d) : "l"(a), "l"(b), "l"(c));
    return d;
}

// ---------------------------------------------------------------------------
__global__ void zero_deg_kernel(float* __restrict__ deg, int N) {
    int i = blockIdx.x * blockDim.x + threadIdx.x;
    if (i < N) deg[i] = 0.0f;
}

__global__ void count_deg_kernel(const int* __restrict__ ei,
                                 float* __restrict__ deg, int E) {
    int e = blockIdx.x * blockDim.x + threadIdx.x;
    if (e < E) atomicAdd(&deg[ei[E + e]], 1.0f);  // dst row
}

// ---------------------------------------------------------------------------
// C[N,128] = A[N,K] @ W[K,128]   (K = 64 or 128, row-major W)
// optional: C += (deg[row]+1)*bias[col]; optional relu
// optional: aggOut = relu(C_raw + sw0 + sw1 + sb)   (self-loop agg init)
// 256 threads, tile 128 rows x 128 cols, thread tile 8x8, fp32x2 FMAs.
__global__ __launch_bounds__(256, 2)
void gemm_kernel(const float* __restrict__ A, const float* __restrict__ W,
                 float* __restrict__ C, int N, int K,
                 const float* __restrict__ bias, const float* __restrict__ deg,
                 int relu_flag,
                 float* __restrict__ aggOut,
                 const float* __restrict__ sw0, const float* __restrict__ sw1,
                 const float* __restrict__ sb)
{
    __shared__ float Ws[32][128];        // [k][col]
    __shared__ float As[128][33];        // [row][k], +1 pad

    const int tid = threadIdx.x;
    const int tx = tid & 15;             // col group: 8*tx
    const int ty = tid >> 4;             // row group: 8*ty
    const int row0 = blockIdx.x * 128;

    ull acc[8][4];
#pragma unroll
    for (int r = 0; r < 8; ++r)
#pragma unroll
        for (int p = 0; p < 4; ++p) acc[r][p] = 0ULL;

    for (int k0 = 0; k0 < K; k0 += 32) {
        // W tile 32x128: 1024 float4, coalesced
#pragma unroll
        for (int i = tid; i < 1024; i += 256) {
            int kk = i >> 5, cg = i & 31;
            *(float4*)&Ws[kk][cg * 4] = *(const float4*)&W[(k0 + kk) * 128 + cg * 4];
        }
        // A tile 128x32: 1024 float4 reads, scalar stores into [row][k] (+pad)
#pragma unroll
        for (int i = tid; i < 1024; i += 256) {
            int rr = i >> 3, kg = i & 7;
            int row = row0 + rr;
            float4 v = make_float4(0.f, 0.f, 0.f, 0.f);
            if (row < N) v = *(const float4*)&A[(long long)row * K + k0 + kg * 4];
            As[rr][kg * 4 + 0] = v.x;
            As[rr][kg * 4 + 1] = v.y;
            As[rr][kg * 4 + 2] = v.z;
            As[rr][kg * 4 + 3] = v.w;
        }
        __syncthreads();

#pragma unroll
        for (int k = 0; k < 32; ++k) {
            // 8 cols of W as 4 packed f32x2 (bits loaded directly into reg pairs)
            ulonglong2 wA = *(const ulonglong2*)&Ws[k][tx * 8];
            ulonglong2 wB = *(const ulonglong2*)&Ws[k][tx * 8 + 4];
#pragma unroll
            for (int r = 0; r < 8; ++r) {
                float a = As[ty * 8 + r][k];
                ull aa = pk2(a, a);
                acc[r][0] = fma2(aa, wA.x, acc[r][0]);
                acc[r][1] = fma2(aa, wA.y, acc[r][1]);
                acc[r][2] = fma2(aa, wB.x, acc[r][2]);
                acc[r][3] = fma2(aa, wB.y, acc[r][3]);
            }
        }
        __syncthreads();
    }

    const int c0 = tx * 8;
#pragma unroll
    for (int r = 0; r < 8; ++r) {
        int row = row0 + ty * 8 + r;
        if (row >= N) continue;
        float v[8];
#pragma unroll
        for (int p = 0; p < 4; ++p) upk2(acc[r][p], v[2 * p], v[2 * p + 1]);

        if (aggOut) {
            float4 a0, a1;
            a0.x = fmaxf(v[0] + sw0[c0+0] + sw1[c0+0] + sb[c0+0], 0.f);
            a0.y = fmaxf(v[1] + sw0[c0+1] + sw1[c0+1] + sb[c0+1], 0.f);
            a0.z = fmaxf(v[2] + sw0[c0+2] + sw1[c0+2] + sb[c0+2], 0.f);
            a0.w = fmaxf(v[3] + sw0[c0+3] + sw1[c0+3] + sb[c0+3], 0.f);
            a1.x = fmaxf(v[4] + sw0[c0+4] + sw1[c0+4] + sb[c0+4], 0.f);
            a1.y = fmaxf(v[5] + sw0[c0+5] + sw1[c0+5] + sb[c0+5], 0.f);
            a1.z = fmaxf(v[6] + sw0[c0+6] + sw1[c0+6] + sb[c0+6], 0.f);
            a1.w = fmaxf(v[7] + sw0[c0+7] + sw1[c0+7] + sb[c0+7], 0.f);
            float4* ad = (float4*)&aggOut[(long long)row * 128 + c0];
            ad[0] = a0; ad[1] = a1;
        }
        if (bias) {
            float mult = deg ? (deg[row] + 1.0f) : 1.0f;
#pragma unroll
            for (int j = 0; j < 8; ++j) v[j] += mult * bias[c0 + j];
        }
        if (relu_flag) {
#pragma unroll
            for (int j = 0; j < 8; ++j) v[j] = fmaxf(v[j], 0.f);
        }
        float4* dst = (float4*)&C[(long long)row * 128 + c0];
        dst[0] = make_float4(v[0], v[1], v[2], v[3]);
        dst[1] = make_float4(v[4], v[5], v[6], v[7]);
    }
}

// ---------------------------------------------------------------------------
// Per-edge: agg[dst] += relu(P[src] + ea0*w0 + ea1*w1 + b)   (128 floats)
// One warp per edge; 2-edge software pipeline for MLP; vector red.add.
__global__ __launch_bounds__(256)
void scatter_kernel(const int* __restrict__ ei,
                    const float* __restrict__ ea,
                    const float* __restrict__ P,
                    float* __restrict__ agg,
                    const float* __restrict__ w0,
                    const float* __restrict__ w1,
                    const float* __restrict__ b,
                    int E)
{
    const int lane = threadIdx.x & 31;
    const int c = lane * 4;
    const int warp = blockIdx.x * (blockDim.x >> 5) + (threadIdx.x >> 5);
    const int nwarps = gridDim.x * (blockDim.x >> 5);

    const float4 wa = *(const float4*)(w0 + c);
    const float4 wb = *(const float4*)(w1 + c);
    const float4 bb = *(const float4*)(b + c);

    int e = warp;
    for (; e + nwarps < E; e += 2 * nwarps) {
        int e2 = e + nwarps;
        // issue all loads for both edges first (MLP)
        int src1 = ei[e],      dst1 = ei[E + e];
        int src2 = ei[e2],     dst2 = ei[E + e2];
        float ea10 = ea[2 * e],      ea11 = ea[2 * e + 1];
        float ea20 = ea[2 * e2],     ea21 = ea[2 * e2 + 1];
        float4 p1 = *(const float4*)(P + (long long)src1 * HD + c);
        float4 p2 = *(const float4*)(P + (long long)src2 * HD + c);

        float4 v1, v2;
        v1.x = fmaxf(fmaf(ea10, wa.x, fmaf(ea11, wb.x, p1.x + bb.x)), 0.f);
        v1.y = fmaxf(fmaf(ea10, wa.y, fmaf(ea11, wb.y, p1.y + bb.y)), 0.f);
        v1.z = fmaxf(fmaf(ea10, wa.z, fmaf(ea11, wb.z, p1.z + bb.z)), 0.f);
        v1.w = fmaxf(fmaf(ea10, wa.w, fmaf(ea11, wb.w, p1.w + bb.w)), 0.f);
        v2.x = fmaxf(fmaf(ea20, wa.x, fmaf(ea21, wb.x, p2.x + bb.x)), 0.f);
        v2.y = fmaxf(fmaf(ea20, wa.y, fmaf(ea21, wb.y, p2.y + bb.y)), 0.f);
        v2.z = fmaxf(fmaf(ea20, wa.z, fmaf(ea21, wb.z, p2.z + bb.z)), 0.f);
        v2.w = fmaxf(fmaf(ea20, wa.w, fmaf(ea21, wb.w, p2.w + bb.w)), 0.f);

        float* d1 = agg + (long long)dst1 * HD + c;
        float* d2 = agg + (long long)dst2 * HD + c;
        asm volatile("red.global.add.v4.f32 [%0], {%1,%2,%3,%4};"
                     :: "l"(d1), "f"(v1.x), "f"(v1.y), "f"(v1.z), "f"(v1.w) : "memory");
        asm volatile("red.global.add.v4.f32 [%0], {%1,%2,%3,%4};"
                     :: "l"(d2), "f"(v2.x), "f"(v2.y), "f"(v2.z), "f"(v2.w) : "memory");
    }
    if (e < E) {
        int src = ei[e], dst = ei[E + e];
        float ea0 = ea[2 * e], ea1 = ea[2 * e + 1];
        float4 p = *(const float4*)(P + (long long)src * HD + c);
        float4 v;
        v.x = fmaxf(fmaf(ea0, wa.x, fmaf(ea1, wb.x, p.x + bb.x)), 0.f);
        v.y = fmaxf(fmaf(ea0, wa.y, fmaf(ea1, wb.y, p.y + bb.y)), 0.f);
        v.z = fmaxf(fmaf(ea0, wa.z, fmaf(ea1, wb.z, p.z + bb.z)), 0.f);
        v.w = fmaxf(fmaf(ea0, wa.w, fmaf(ea1, wb.w, p.w + bb.w)), 0.f);
        float* d = agg + (long long)dst * HD + c;
        asm volatile("red.global.add.v4.f32 [%0], {%1,%2,%3,%4};"
                     :: "l"(d), "f"(v.x), "f"(v.y), "f"(v.z), "f"(v.w) : "memory");
    }
}

// ---------------------------------------------------------------------------
extern "C" void kernel_launch(void* const* d_in, const int* in_sizes, int n_in,
                              void* d_out, int out_size)
{
    const float* x   = (const float*)d_in[0];
    const int*   ei  = (const int*)d_in[1];     // int32 edge indices
    const float* ea  = (const float*)d_in[2];
    const float* W11 = (const float*)d_in[3];
    const float* b11 = (const float*)d_in[4];
    const float* W12 = (const float*)d_in[5];
    const float* b12 = (const float*)d_in[6];
    const float* W21 = (const float*)d_in[7];
    const float* b21 = (const float*)d_in[8];
    const float* W22 = (const float*)d_in[9];
    const float* b22 = (const float*)d_in[10];
    float* out = (float*)d_out;

    const int IN_DIM = 64;
    const int N = in_sizes[0] / IN_DIM;
    const int E = in_sizes[1] / 2;

    float* P   = nullptr;
    float* agg = nullptr;
    float* h   = nullptr;
    float* deg = nullptr;
    cudaGetSymbolAddress((void**)&P,   g_P);
    cudaGetSymbolAddress((void**)&agg, g_agg);
    cudaGetSymbolAddress((void**)&h,   g_h);
    cudaGetSymbolAddress((void**)&deg, g_deg);

    const int gemm_blocks = (N + 127) / 128;
    const int scat_blocks = 148 * 16;

    // degrees (same graph both layers)
    zero_deg_kernel<<<(N + 255) / 256, 256>>>(deg, N);
    count_deg_kernel<<<(E + 255) / 256, 256>>>(ei, deg, E);

    // ---- layer 1 ----
    gemm_kernel<<<gemm_blocks, 256>>>(x, W11, P, N, 64,
                                      nullptr, nullptr, 0,
                                      agg, W11 + 64 * 128, W11 + 65 * 128, b11);
    scatter_kernel<<<scat_blocks, 256>>>(ei, ea, P, agg,
                                         W11 + 64 * 128, W11 + 65 * 128, b11, E);
    gemm_kernel<<<gemm_blocks, 256>>>(agg, W12, h, N, 128,
                                      b12, deg, 1,
                                      nullptr, nullptr, nullptr, nullptr);

    // ---- layer 2 ----
    gemm_kernel<<<gemm_blocks, 256>>>(h, W21, P, N, 128,
                                      nullptr, nullptr, 0,
                                      agg, W21 + 128 * 128, W21 + 129 * 128, b21);
    scatter_kernel<<<scat_blocks, 256>>>(ei, ea, P, agg,
                                         W21 + 128 * 128, W21 + 129 * 128, b21, E);
    gemm_kernel<<<gemm_blocks, 256>>>(agg, W22, out, N, 128,
                                      b22, deg, 0,
                                      nullptr, nullptr, nullptr, nullptr);
}

// round 4
// speedup vs baseline: 1.2946x; 1.0722x over previous
#include <cuda_runtime.h>

// GIN model, algebraically restructured:
//   conv(x) = segment_sum(relu(x[src]@W1x + ea@W1e + b1), dst) @ W2 + (deg+1) * b2
// Per-node GEMMs (fp32x2 packed FMA, cp.async double-buffered) +
// per-edge gather/scatter (L2-resident tables).

#define HD 128
#define MAX_N 100000
#define MAX_E 1600000

__device__ float g_P[(long long)MAX_N * HD];    // per-node pre-MLP table
__device__ float g_agg[(long long)MAX_N * HD];  // aggregation buffer
__device__ float g_h[(long long)MAX_N * HD];    // layer-1 output
__device__ float g_deg[MAX_N];                  // in-degree (float)

typedef unsigned long long ull;

__device__ __forceinline__ ull pk2(float x, float y) {
    ull r; asm("mov.b64 %0, {%1, %2};" : "=l"(r) : "f"(x), "f"(y)); return r;
}
__device__ __forceinline__ void upk2(ull v, float& x, float& y) {
    asm("mov.b64 {%0, %1}, %2;" : "=f"(x), "=f"(y) : "l"(v));
}
__device__ __forceinline__ ull fma2(ull a, ull b, ull c) {
    ull d; asm("fma.rn.f32x2 %0, %1, %2, %3;" : "=l"(d) : "l"(a), "l"(b), "l"(c));
    return d;
}
__device__ __forceinline__ void cp16(void* smem_dst, const void* gsrc, int src_bytes) {
    unsigned s = (unsigned)__cvta_generic_to_shared(smem_dst);
    asm volatile("cp.async.ca.shared.global [%0], [%1], 16, %2;"
                 :: "r"(s), "l"(gsrc), "r"(src_bytes));
}
__device__ __forceinline__ void cp_commit() {
    asm volatile("cp.async.commit_group;");
}
template <int NN>
__device__ __forceinline__ void cp_wait() {
    asm volatile("cp.async.wait_group %0;" :: "n"(NN));
}

// ---------------------------------------------------------------------------
__global__ void zero_deg_kernel(float* __restrict__ deg, int N) {
    int i = blockIdx.x * blockDim.x + threadIdx.x;
    if (i < N) deg[i] = 0.0f;
}

__global__ void count_deg_kernel(const int* __restrict__ ei,
                                 float* __restrict__ deg, int E) {
    int e = blockIdx.x * blockDim.x + threadIdx.x;
    if (e < E) atomicAdd(&deg[ei[E + e]], 1.0f);  // dst row
}

// ---------------------------------------------------------------------------
// C[N,128] = A[N,K] @ W[K,128]   (K = 64 or 128, row-major W)
// optional: C += (deg[row]+1)*bias[col]; optional relu
// optional: aggOut = relu(C_raw + sw0 + sw1 + sb)   (self-loop agg init)
// 256 threads, tile 128x128, thread tile 8x8, fp32x2 FMAs, cp.async 2-stage.
#define AS_LD 36   // 32 + 4 pad: bank=(4*row+k)%32 -> conflict-free per-k reads

__global__ __launch_bounds__(256, 2)
void gemm_kernel(const float* __restrict__ A, const float* __restrict__ W,
                 float* __restrict__ C, int N, int K,
                 const float* __restrict__ bias, const float* __restrict__ deg,
                 int relu_flag,
                 float* __restrict__ aggOut,
                 const float* __restrict__ sw0, const float* __restrict__ sw1,
                 const float* __restrict__ sb)
{
    __shared__ float Ws[2][32][128];     // [buf][k][col]
    __shared__ float As[2][128][AS_LD];  // [buf][row][k]

    const int tid = threadIdx.x;
    const int tx = tid & 15;             // col group: 8*tx
    const int ty = tid >> 4;             // row group: 8*ty
    const int row0 = blockIdx.x * 128;

    // per-thread load coords (4 x 16B for W, 4 x 16B for A per tile)
    const int wk = tid >> 5;             // 0..7 : k rows (then +8 each iter x4)
    const int wc = (tid & 31) * 4;       // col within W row... (32 lanes * 4 fl = 128)
    const int ar = tid >> 1;             // 0..127 : A row
    const int ak = (tid & 1) * 16;       // k offset 0 or 16 (then +4 each of 4)

    ull acc[8][4];
#pragma unroll
    for (int r = 0; r < 8; ++r)
#pragma unroll
        for (int p = 0; p < 4; ++p) acc[r][p] = 0ULL;

    const int nt = K >> 5;               // number of 32-wide k tiles

    // ---- tile loader (cp.async only) ----
    auto load_tile = [&](int buf, int k0) {
        // W tile 32x128: each thread 4 rows (wk, wk+8, wk+16, wk+24), 16B each
#pragma unroll
        for (int j = 0; j < 4; ++j) {
            int kk = wk + j * 8;
            cp16(&Ws[buf][kk][wc], &W[(k0 + kk) * 128 + wc], 16);
        }
        // A tile 128x32: each thread one row, two 16B chunks... (2 threads/row)
#pragma unroll
        for (int j = 0; j < 1; ++j) { }
        int row = row0 + ar;
        int ok = (row < N) ? 16 : 0;
        const float* ap = &A[(long long)row * K + k0 + ak];
        cp16(&As[buf][ar][ak + 0],  ap + 0,  ok);
        cp16(&As[buf][ar][ak + 4],  ap + 4,  ok);
        cp16(&As[buf][ar][ak + 8],  ap + 8,  ok);
        cp16(&As[buf][ar][ak + 12], ap + 12, ok);
    };

    load_tile(0, 0);
    cp_commit();

    for (int t = 0; t < nt; ++t) {
        const int buf = t & 1;
        if (t + 1 < nt) {
            load_tile(buf ^ 1, (t + 1) * 32);
            cp_commit();
            cp_wait<1>();
        } else {
            cp_wait<0>();
        }
        __syncthreads();

#pragma unroll
        for (int k = 0; k < 32; ++k) {
            ulonglong2 wA = *(const ulonglong2*)&Ws[buf][k][tx * 8];
            ulonglong2 wB = *(const ulonglong2*)&Ws[buf][k][tx * 8 + 4];
#pragma unroll
            for (int r = 0; r < 8; ++r) {
                float a = As[buf][ty * 8 + r][k];
                ull aa = pk2(a, a);
                acc[r][0] = fma2(aa, wA.x, acc[r][0]);
                acc[r][1] = fma2(aa, wA.y, acc[r][1]);
                acc[r][2] = fma2(aa, wB.x, acc[r][2]);
                acc[r][3] = fma2(aa, wB.y, acc[r][3]);
            }
        }
        __syncthreads();
    }

    const int c0 = tx * 8;
#pragma unroll
    for (int r = 0; r < 8; ++r) {
        int row = row0 + ty * 8 + r;
        if (row >= N) continue;
        float v[8];
#pragma unroll
        for (int p = 0; p < 4; ++p) upk2(acc[r][p], v[2 * p], v[2 * p + 1]);

        if (aggOut) {
            float4 a0, a1;
            a0.x = fmaxf(v[0] + sw0[c0+0] + sw1[c0+0] + sb[c0+0], 0.f);
            a0.y = fmaxf(v[1] + sw0[c0+1] + sw1[c0+1] + sb[c0+1], 0.f);
            a0.z = fmaxf(v[2] + sw0[c0+2] + sw1[c0+2] + sb[c0+2], 0.f);
            a0.w = fmaxf(v[3] + sw0[c0+3] + sw1[c0+3] + sb[c0+3], 0.f);
            a1.x = fmaxf(v[4] + sw0[c0+4] + sw1[c0+4] + sb[c0+4], 0.f);
            a1.y = fmaxf(v[5] + sw0[c0+5] + sw1[c0+5] + sb[c0+5], 0.f);
            a1.z = fmaxf(v[6] + sw0[c0+6] + sw1[c0+6] + sb[c0+6], 0.f);
            a1.w = fmaxf(v[7] + sw0[c0+7] + sw1[c0+7] + sb[c0+7], 0.f);
            float4* ad = (float4*)&aggOut[(long long)row * 128 + c0];
            ad[0] = a0; ad[1] = a1;
        }
        if (bias) {
            float mult = deg ? (deg[row] + 1.0f) : 1.0f;
#pragma unroll
            for (int j = 0; j < 8; ++j) v[j] += mult * bias[c0 + j];
        }
        if (relu_flag) {
#pragma unroll
            for (int j = 0; j < 8; ++j) v[j] = fmaxf(v[j], 0.f);
        }
        float4* dst = (float4*)&C[(long long)row * 128 + c0];
        dst[0] = make_float4(v[0], v[1], v[2], v[3]);
        dst[1] = make_float4(v[4], v[5], v[6], v[7]);
    }
}

// ---------------------------------------------------------------------------
// Per-edge: agg[dst] += relu(P[src] + ea0*w0 + ea1*w1 + b)   (128 floats)
// One warp per edge, lane handles 4 consecutive floats, vector red.add.
__global__ __launch_bounds__(256)
void scatter_kernel(const int* __restrict__ ei,
                    const float* __restrict__ ea,
                    const float* __restrict__ P,
                    float* __restrict__ agg,
                    const float* __restrict__ w0,
                    const float* __restrict__ w1,
                    const float* __restrict__ b,
                    int E)
{
    const int lane = threadIdx.x & 31;
    const int c = lane * 4;
    const int warp = blockIdx.x * (blockDim.x >> 5) + (threadIdx.x >> 5);
    const int nwarps = gridDim.x * (blockDim.x >> 5);

    const float4 wa = *(const float4*)(w0 + c);
    const float4 wb = *(const float4*)(w1 + c);
    const float4 bb = *(const float4*)(b + c);

    for (int e = warp; e < E; e += nwarps) {
        int src = ei[e];
        int dst = ei[E + e];
        float ea0 = ea[2 * e];
        float ea1 = ea[2 * e + 1];
        float4 p = *(const float4*)(P + (long long)src * HD + c);
        float4 v;
        v.x = fmaxf(fmaf(ea0, wa.x, fmaf(ea1, wb.x, p.x + bb.x)), 0.0f);
        v.y = fmaxf(fmaf(ea0, wa.y, fmaf(ea1, wb.y, p.y + bb.y)), 0.0f);
        v.z = fmaxf(fmaf(ea0, wa.z, fmaf(ea1, wb.z, p.z + bb.z)), 0.0f);
        v.w = fmaxf(fmaf(ea0, wa.w, fmaf(ea1, wb.w, p.w + bb.w)), 0.0f);
        float* d = agg + (long long)dst * HD + c;
        asm volatile("red.global.add.v4.f32 [%0], {%1,%2,%3,%4};"
                     :: "l"(d), "f"(v.x), "f"(v.y), "f"(v.z), "f"(v.w)
                     : "memory");
    }
}

// ---------------------------------------------------------------------------
extern "C" void kernel_launch(void* const* d_in, const int* in_sizes, int n_in,
                              void* d_out, int out_size)
{
    const float* x   = (const float*)d_in[0];
    const int*   ei  = (const int*)d_in[1];     // int32 edge indices
    const float* ea  = (const float*)d_in[2];
    const float* W11 = (const float*)d_in[3];
    const float* b11 = (const float*)d_in[4];
    const float* W12 = (const float*)d_in[5];
    const float* b12 = (const float*)d_in[6];
    const float* W21 = (const float*)d_in[7];
    const float* b21 = (const float*)d_in[8];
    const float* W22 = (const float*)d_in[9];
    const float* b22 = (const float*)d_in[10];
    float* out = (float*)d_out;

    const int IN_DIM = 64;
    const int N = in_sizes[0] / IN_DIM;
    const int E = in_sizes[1] / 2;

    float* P   = nullptr;
    float* agg = nullptr;
    float* h   = nullptr;
    float* deg = nullptr;
    cudaGetSymbolAddress((void**)&P,   g_P);
    cudaGetSymbolAddress((void**)&agg, g_agg);
    cudaGetSymbolAddress((void**)&h,   g_h);
    cudaGetSymbolAddress((void**)&deg, g_deg);

    const int gemm_blocks = (N + 127) / 128;
    const int scat_blocks = 148 * 16;

    // degrees (same graph both layers)
    zero_deg_kernel<<<(N + 255) / 256, 256>>>(deg, N);
    count_deg_kernel<<<(E + 255) / 256, 256>>>(ei, deg, E);

    // ---- layer 1 ----
    gemm_kernel<<<gemm_blocks, 256>>>(x, W11, P, N, 64,
                                      nullptr, nullptr, 0,
                                      agg, W11 + 64 * 128, W11 + 65 * 128, b11);
    scatter_kernel<<<scat_blocks, 256>>>(ei, ea, P, agg,
                                         W11 + 64 * 128, W11 + 65 * 128, b11, E);
    gemm_kernel<<<gemm_blocks, 256>>>(agg, W12, h, N, 128,
                                      b12, deg, 1,
                                      nullptr, nullptr, nullptr, nullptr);

    // ---- layer 2 ----
    gemm_kernel<<<gemm_blocks, 256>>>(h, W21, P, N, 128,
                                      nullptr, nullptr, 0,
                                      agg, W21 + 128 * 128, W21 + 129 * 128, b21);
    scatter_kernel<<<scat_blocks, 256>>>(ei, ea, P, agg,
                                         W21 + 128 * 128, W21 + 129 * 128, b21, E);
    gemm_kernel<<<gemm_blocks, 256>>>(agg, W22, out, N, 128,
                                      b22, deg, 0,
                                      nullptr, nullptr, nullptr, nullptr);
}

// round 5
// speedup vs baseline: 1.6585x; 1.2811x over previous
#include <cuda_runtime.h>

// GIN model, algebraically restructured:
//   conv(x) = segment_sum(relu(x[src]@W1x + ea@W1e + b1), dst) @ W2 + (deg+1) * b2
// Per-node GEMMs (fp32x2 packed FMA, cp.async) + CSR-bucketed atomic-free
// per-edge gather + per-node register accumulation.

#define HD 128
#define MAX_N 100000
#define MAX_E 1600000

__device__ float g_P[(long long)MAX_N * HD];    // per-node pre-MLP table
__device__ float g_agg[(long long)MAX_N * HD];  // aggregation buffer
__device__ float g_h[(long long)MAX_N * HD];    // layer-1 output
__device__ int    g_cnt[MAX_N];                 // per-dst edge counts
__device__ int    g_fill[MAX_N];                // fill cursors
__device__ int    g_rowptr[MAX_N + 1];          // CSR row pointers (by dst)
__device__ int    g_bsum[128];                  // scan block sums
__device__ int    g_boff[128];                  // scan block offsets
__device__ int    g_src[MAX_E];                 // CSR: source node per slot
__device__ float2 g_eas[MAX_E];                 // CSR: edge attr per slot

typedef unsigned long long ull;

__device__ __forceinline__ ull pk2(float x, float y) {
    ull r; asm("mov.b64 %0, {%1, %2};" : "=l"(r) : "f"(x), "f"(y)); return r;
}
__device__ __forceinline__ void upk2(ull v, float& x, float& y) {
    asm("mov.b64 {%0, %1}, %2;" : "=f"(x), "=f"(y) : "l"(v));
}
__device__ __forceinline__ ull fma2(ull a, ull b, ull c) {
    ull d; asm("fma.rn.f32x2 %0, %1, %2, %3;" : "=l"(d) : "l"(a), "l"(b), "l"(c));
    return d;
}
__device__ __forceinline__ void cp16(void* smem_dst, const void* gsrc, int src_bytes) {
    unsigned s = (unsigned)__cvta_generic_to_shared(smem_dst);
    asm volatile("cp.async.ca.shared.global [%0], [%1], 16, %2;"
                 :: "r"(s), "l"(gsrc), "r"(src_bytes));
}
__device__ __forceinline__ void cp_commit() { asm volatile("cp.async.commit_group;"); }
template <int NN>
__device__ __forceinline__ void cp_wait() {
    asm volatile("cp.async.wait_group %0;" :: "n"(NN));
}

// ============================== CSR build ==================================
__global__ void zero_cnt_kernel(int* __restrict__ cnt, int* __restrict__ fill, int N) {
    int i = blockIdx.x * blockDim.x + threadIdx.x;
    if (i < N) { cnt[i] = 0; fill[i] = 0; }
}

__global__ void count_kernel(const int* __restrict__ ei, int* __restrict__ cnt, int E) {
    int e = blockIdx.x * blockDim.x + threadIdx.x;
    if (e < E) atomicAdd(&cnt[ei[E + e]], 1);
}

// block sums over 1024-element chunks
__global__ void scan_reduce_kernel(const int* __restrict__ cnt, int* __restrict__ bsum, int N) {
    __shared__ int sh[256];
    int base = blockIdx.x * 1024;
    int s = 0;
    for (int i = threadIdx.x; i < 1024; i += 256) {
        int idx = base + i;
        if (idx < N) s += cnt[idx];
    }
    sh[threadIdx.x] = s; __syncthreads();
    for (int off = 128; off > 0; off >>= 1) {
        if (threadIdx.x < off) sh[threadIdx.x] += sh[threadIdx.x + off];
        __syncthreads();
    }
    if (threadIdx.x == 0) bsum[blockIdx.x] = sh[0];
}

__global__ void scan_bsums_kernel(const int* __restrict__ bsum, int* __restrict__ boff,
                                  int nb, int* __restrict__ rowptr, int N, int E) {
    if (threadIdx.x == 0) {
        int run = 0;
        for (int i = 0; i < nb; ++i) { boff[i] = run; run += bsum[i]; }
        rowptr[N] = E;
    }
}

// per-chunk exclusive scan (1024 threads)
__global__ void scan_block_kernel(const int* __restrict__ cnt, const int* __restrict__ boff,
                                  int* __restrict__ rowptr, int N) {
    __shared__ int sh[1024];
    const int tid = threadIdx.x;
    const int idx = blockIdx.x * 1024 + tid;
    int v = (idx < N) ? cnt[idx] : 0;
    sh[tid] = v; __syncthreads();
#pragma unroll
    for (int off = 1; off < 1024; off <<= 1) {
        int t = (tid >= off) ? sh[tid - off] : 0;
        __syncthreads();
        sh[tid] += t;
        __syncthreads();
    }
    if (idx < N) rowptr[idx] = boff[blockIdx.x] + sh[tid] - v;  // exclusive
}

__global__ void fill_kernel(const int* __restrict__ ei, const float* __restrict__ ea,
                            const int* __restrict__ rowptr, int* __restrict__ fill,
                            int* __restrict__ srcs, float2* __restrict__ eas, int E) {
    int e = blockIdx.x * blockDim.x + threadIdx.x;
    if (e >= E) return;
    int dst = ei[E + e];
    int slot = rowptr[dst] + atomicAdd(&fill[dst], 1);
    srcs[slot] = ei[e];
    eas[slot] = make_float2(ea[2 * e], ea[2 * e + 1]);
}

// ================================ GEMM =====================================
// C[N,128] = A[N,K] @ W[K,128]; optional (deg+1)*bias (deg from rowptr) + relu.
#define AS_LD 36

__global__ __launch_bounds__(256, 2)
void gemm_kernel(const float* __restrict__ A, const float* __restrict__ W,
                 float* __restrict__ C, int N, int K,
                 const float* __restrict__ bias, const int* __restrict__ rowptr,
                 int relu_flag)
{
    __shared__ float Ws[2][32][128];
    __shared__ float As[2][128][AS_LD];

    const int tid = threadIdx.x;
    const int tx = tid & 15;
    const int ty = tid >> 4;
    const int row0 = blockIdx.x * 128;

    const int wk = tid >> 5;
    const int wc = (tid & 31) * 4;
    const int ar = tid >> 1;
    const int ak = (tid & 1) * 16;

    ull acc[8][4];
#pragma unroll
    for (int r = 0; r < 8; ++r)
#pragma unroll
        for (int p = 0; p < 4; ++p) acc[r][p] = 0ULL;

    const int nt = K >> 5;

    auto load_tile = [&](int buf, int k0) {
#pragma unroll
        for (int j = 0; j < 4; ++j) {
            int kk = wk + j * 8;
            cp16(&Ws[buf][kk][wc], &W[(k0 + kk) * 128 + wc], 16);
        }
        int row = row0 + ar;
        int ok = (row < N) ? 16 : 0;
        const float* ap = &A[(long long)row * K + k0 + ak];
        cp16(&As[buf][ar][ak + 0],  ap + 0,  ok);
        cp16(&As[buf][ar][ak + 4],  ap + 4,  ok);
        cp16(&As[buf][ar][ak + 8],  ap + 8,  ok);
        cp16(&As[buf][ar][ak + 12], ap + 12, ok);
    };

    load_tile(0, 0);
    cp_commit();

    for (int t = 0; t < nt; ++t) {
        const int buf = t & 1;
        if (t + 1 < nt) {
            load_tile(buf ^ 1, (t + 1) * 32);
            cp_commit();
            cp_wait<1>();
        } else {
            cp_wait<0>();
        }
        __syncthreads();
#pragma unroll
        for (int k = 0; k < 32; ++k) {
            ulonglong2 wA = *(const ulonglong2*)&Ws[buf][k][tx * 8];
            ulonglong2 wB = *(const ulonglong2*)&Ws[buf][k][tx * 8 + 4];
#pragma unroll
            for (int r = 0; r < 8; ++r) {
                float a = As[buf][ty * 8 + r][k];
                ull aa = pk2(a, a);
                acc[r][0] = fma2(aa, wA.x, acc[r][0]);
                acc[r][1] = fma2(aa, wA.y, acc[r][1]);
                acc[r][2] = fma2(aa, wB.x, acc[r][2]);
                acc[r][3] = fma2(aa, wB.y, acc[r][3]);
            }
        }
        __syncthreads();
    }

    const int c0 = tx * 8;
#pragma unroll
    for (int r = 0; r < 8; ++r) {
        int row = row0 + ty * 8 + r;
        if (row >= N) continue;
        float v[8];
#pragma unroll
        for (int p = 0; p < 4; ++p) upk2(acc[r][p], v[2 * p], v[2 * p + 1]);
        if (bias) {
            float mult = 1.0f;
            if (rowptr) mult = (float)(rowptr[row + 1] - rowptr[row]) + 1.0f;
#pragma unroll
            for (int j = 0; j < 8; ++j) v[j] += mult * bias[c0 + j];
        }
        if (relu_flag) {
#pragma unroll
            for (int j = 0; j < 8; ++j) v[j] = fmaxf(v[j], 0.f);
        }
        float4* dst = (float4*)&C[(long long)row * 128 + c0];
        dst[0] = make_float4(v[0], v[1], v[2], v[3]);
        dst[1] = make_float4(v[4], v[5], v[6], v[7]);
    }
}

// ========================= CSR gather-aggregate ============================
// One warp per dst node: acc = relu(P[n]+w0+w1+b)  (self loop, ea=1)
//                        acc += relu(P[src]+ea0*w0+ea1*w1+b)  per in-edge
// plain vector store, no atomics. 4-edge batching for MLP.
__global__ __launch_bounds__(256)
void gather_kernel(const int* __restrict__ rowptr, const int* __restrict__ srcs,
                   const float2* __restrict__ eas,
                   const float* __restrict__ P, float* __restrict__ agg,
                   const float* __restrict__ w0, const float* __restrict__ w1,
                   const float* __restrict__ b, int N)
{
    const int lane = threadIdx.x & 31;
    const int c = lane * 4;
    const int warp = blockIdx.x * (blockDim.x >> 5) + (threadIdx.x >> 5);
    const int nwarps = gridDim.x * (blockDim.x >> 5);

    const float4 wa = *(const float4*)(w0 + c);
    const float4 wb = *(const float4*)(w1 + c);
    const float4 bb = *(const float4*)(b + c);

    for (int n = warp; n < N; n += nwarps) {
        const int s = rowptr[n];
        const int e = rowptr[n + 1];

        // self loop (ea = 1,1)
        float4 ps = *(const float4*)(P + (long long)n * HD + c);
        float4 acc;
        acc.x = fmaxf(ps.x + wa.x + wb.x + bb.x, 0.f);
        acc.y = fmaxf(ps.y + wa.y + wb.y + bb.y, 0.f);
        acc.z = fmaxf(ps.z + wa.z + wb.z + bb.z, 0.f);
        acc.w = fmaxf(ps.w + wa.w + wb.w + bb.w, 0.f);

        int j = s;
        for (; j + 4 <= e; j += 4) {
            int s0 = srcs[j], s1 = srcs[j + 1], s2 = srcs[j + 2], s3 = srcs[j + 3];
            float2 e0 = eas[j], e1 = eas[j + 1], e2 = eas[j + 2], e3 = eas[j + 3];
            float4 p0 = *(const float4*)(P + (long long)s0 * HD + c);
            float4 p1 = *(const float4*)(P + (long long)s1 * HD + c);
            float4 p2 = *(const float4*)(P + (long long)s2 * HD + c);
            float4 p3 = *(const float4*)(P + (long long)s3 * HD + c);
            acc.x += fmaxf(fmaf(e0.x, wa.x, fmaf(e0.y, wb.x, p0.x + bb.x)), 0.f);
            acc.y += fmaxf(fmaf(e0.x, wa.y, fmaf(e0.y, wb.y, p0.y + bb.y)), 0.f);
            acc.z += fmaxf(fmaf(e0.x, wa.z, fmaf(e0.y, wb.z, p0.z + bb.z)), 0.f);
            acc.w += fmaxf(fmaf(e0.x, wa.w, fmaf(e0.y, wb.w, p0.w + bb.w)), 0.f);
            acc.x += fmaxf(fmaf(e1.x, wa.x, fmaf(e1.y, wb.x, p1.x + bb.x)), 0.f);
            acc.y += fmaxf(fmaf(e1.x, wa.y, fmaf(e1.y, wb.y, p1.y + bb.y)), 0.f);
            acc.z += fmaxf(fmaf(e1.x, wa.z, fmaf(e1.y, wb.z, p1.z + bb.z)), 0.f);
            acc.w += fmaxf(fmaf(e1.x, wa.w, fmaf(e1.y, wb.w, p1.w + bb.w)), 0.f);
            acc.x += fmaxf(fmaf(e2.x, wa.x, fmaf(e2.y, wb.x, p2.x + bb.x)), 0.f);
            acc.y += fmaxf(fmaf(e2.x, wa.y, fmaf(e2.y, wb.y, p2.y + bb.y)), 0.f);
            acc.z += fmaxf(fmaf(e2.x, wa.z, fmaf(e2.y, wb.z, p2.z + bb.z)), 0.f);
            acc.w += fmaxf(fmaf(e2.x, wa.w, fmaf(e2.y, wb.w, p2.w + bb.w)), 0.f);
            acc.x += fmaxf(fmaf(e3.x, wa.x, fmaf(e3.y, wb.x, p3.x + bb.x)), 0.f);
            acc.y += fmaxf(fmaf(e3.x, wa.y, fmaf(e3.y, wb.y, p3.y + bb.y)), 0.f);
            acc.z += fmaxf(fmaf(e3.x, wa.z, fmaf(e3.y, wb.z, p3.z + bb.z)), 0.f);
            acc.w += fmaxf(fmaf(e3.x, wa.w, fmaf(e3.y, wb.w, p3.w + bb.w)), 0.f);
        }
        for (; j < e; ++j) {
            int sj = srcs[j];
            float2 ej = eas[j];
            float4 p = *(const float4*)(P + (long long)sj * HD + c);
            acc.x += fmaxf(fmaf(ej.x, wa.x, fmaf(ej.y, wb.x, p.x + bb.x)), 0.f);
            acc.y += fmaxf(fmaf(ej.x, wa.y, fmaf(ej.y, wb.y, p.y + bb.y)), 0.f);
            acc.z += fmaxf(fmaf(ej.x, wa.z, fmaf(ej.y, wb.z, p.z + bb.z)), 0.f);
            acc.w += fmaxf(fmaf(ej.x, wa.w, fmaf(ej.y, wb.w, p.w + bb.w)), 0.f);
        }
        *(float4*)(agg + (long long)n * HD + c) = acc;
    }
}

// ---------------------------------------------------------------------------
extern "C" void kernel_launch(void* const* d_in, const int* in_sizes, int n_in,
                              void* d_out, int out_size)
{
    const float* x   = (const float*)d_in[0];
    const int*   ei  = (const int*)d_in[1];     // int32 edge indices
    const float* ea  = (const float*)d_in[2];
    const float* W11 = (const float*)d_in[3];
    const float* b11 = (const float*)d_in[4];
    const float* W12 = (const float*)d_in[5];
    const float* b12 = (const float*)d_in[6];
    const float* W21 = (const float*)d_in[7];
    const float* b21 = (const float*)d_in[8];
    const float* W22 = (const float*)d_in[9];
    const float* b22 = (const float*)d_in[10];
    float* out = (float*)d_out;

    const int IN_DIM = 64;
    const int N = in_sizes[0] / IN_DIM;
    const int E = in_sizes[1] / 2;

    float *P, *agg, *h;
    int *cnt, *fill, *rowptr, *bsum, *boff, *srcs;
    float2* eas;
    cudaGetSymbolAddress((void**)&P,      g_P);
    cudaGetSymbolAddress((void**)&agg,    g_agg);
    cudaGetSymbolAddress((void**)&h,      g_h);
    cudaGetSymbolAddress((void**)&cnt,    g_cnt);
    cudaGetSymbolAddress((void**)&fill,   g_fill);
    cudaGetSymbolAddress((void**)&rowptr, g_rowptr);
    cudaGetSymbolAddress((void**)&bsum,   g_bsum);
    cudaGetSymbolAddress((void**)&boff,   g_boff);
    cudaGetSymbolAddress((void**)&srcs,   g_src);
    cudaGetSymbolAddress((void**)&eas,    g_eas);

    const int gemm_blocks = (N + 127) / 128;
    const int gath_blocks = 148 * 16;
    const int nb = (N + 1023) / 1024;

    // ---- CSR build (by dst), shared by both layers ----
    zero_cnt_kernel<<<(N + 255) / 256, 256>>>(cnt, fill, N);
    count_kernel<<<(E + 255) / 256, 256>>>(ei, cnt, E);
    scan_reduce_kernel<<<nb, 256>>>(cnt, bsum, N);
    scan_bsums_kernel<<<1, 32>>>(bsum, boff, nb, rowptr, N, E);
    scan_block_kernel<<<nb, 1024>>>(cnt, boff, rowptr, N);
    fill_kernel<<<(E + 255) / 256, 256>>>(ei, ea, rowptr, fill, srcs, eas, E);

    // ---- layer 1 ----
    gemm_kernel<<<gemm_blocks, 256>>>(x, W11, P, N, 64, nullptr, nullptr, 0);
    gather_kernel<<<gath_blocks, 256>>>(rowptr, srcs, eas, P, agg,
                                        W11 + 64 * 128, W11 + 65 * 128, b11, N);
    gemm_kernel<<<gemm_blocks, 256>>>(agg, W12, h, N, 128, b12, rowptr, 1);

    // ---- layer 2 ----
    gemm_kernel<<<gemm_blocks, 256>>>(h, W21, P, N, 128, nullptr, nullptr, 0);
    gather_kernel<<<gath_blocks, 256>>>(rowptr, srcs, eas, P, agg,
                                        W21 + 128 * 128, W21 + 129 * 128, b21, N);
    gemm_kernel<<<gemm_blocks, 256>>>(agg, W22, out, N, 128, b22, rowptr, 0);
}